// round 1
// baseline (speedup 1.0000x reference)
#include <cuda_runtime.h>

// Problem constants
#define B_   4
#define T_   1024
#define E_   512
#define H_   8
#define L_   4
#define V_   32000
#define HID_ 100
#define HD_  64
#define BT_  (B_*T_)

// ---------------- scratch (no allocations allowed) ----------------
__device__ float g_x[BT_*E_];
__device__ float g_h[BT_*E_];
__device__ float g_q[BT_*E_];
__device__ float g_k[BT_*E_];
__device__ float g_v[BT_*E_];
__device__ float g_y[BT_*E_];
__device__ float g_m[BT_*HID_];

// ---------------- block reductions ----------------
__device__ __forceinline__ float blockReduceSum(float v) {
    __shared__ float sh[32];
    int lane = threadIdx.x & 31, w = threadIdx.x >> 5;
    #pragma unroll
    for (int o = 16; o > 0; o >>= 1) v += __shfl_xor_sync(0xffffffffu, v, o);
    if (lane == 0) sh[w] = v;
    __syncthreads();
    v = (threadIdx.x < (blockDim.x >> 5)) ? sh[threadIdx.x] : 0.f;
    if (w == 0) {
        #pragma unroll
        for (int o = 16; o > 0; o >>= 1) v += __shfl_xor_sync(0xffffffffu, v, o);
        if (lane == 0) sh[0] = v;
    }
    __syncthreads();
    float r = sh[0];
    __syncthreads();
    return r;
}

__device__ __forceinline__ float blockReduceMax(float v) {
    __shared__ float sh[32];
    int lane = threadIdx.x & 31, w = threadIdx.x >> 5;
    #pragma unroll
    for (int o = 16; o > 0; o >>= 1) v = fmaxf(v, __shfl_xor_sync(0xffffffffu, v, o));
    if (lane == 0) sh[w] = v;
    __syncthreads();
    v = (threadIdx.x < (blockDim.x >> 5)) ? sh[threadIdx.x] : -1e30f;
    if (w == 0) {
        #pragma unroll
        for (int o = 16; o > 0; o >>= 1) v = fmaxf(v, __shfl_xor_sync(0xffffffffu, v, o));
        if (lane == 0) sh[0] = v;
    }
    __syncthreads();
    float r = sh[0];
    __syncthreads();
    return r;
}

// ---------------- embedding ----------------
__global__ void embed_k(const int* __restrict__ idx, const float* __restrict__ tok,
                        const float* __restrict__ pos, float* __restrict__ x) {
    int i = blockIdx.x * 256 + threadIdx.x;
    if (i >= BT_*E_) return;
    int e  = i & (E_-1);
    int bt = i >> 9;          // /E_
    int t  = bt & (T_-1);
    x[i] = tok[(long long)idx[bt]*E_ + e] + pos[t*E_ + e];
}

// ---------------- layernorm (one block per row, 256 threads, E=512) ----------------
__global__ void layernorm_k(const float* __restrict__ x, const float* __restrict__ g,
                            const float* __restrict__ bb, float* __restrict__ out) {
    const float* xr = x + (long long)blockIdx.x * E_;
    float v0 = xr[threadIdx.x], v1 = xr[threadIdx.x + 256];
    float mean = blockReduceSum(v0 + v1) * (1.f / E_);
    float d0 = v0 - mean, d1 = v1 - mean;
    float var = blockReduceSum(d0*d0 + d1*d1) * (1.f / E_);
    float rstd = rsqrtf(var + 1e-5f);
    float* o = out + (long long)blockIdx.x * E_;
    o[threadIdx.x]       = d0 * rstd * g[threadIdx.x]       + bb[threadIdx.x];
    o[threadIdx.x + 256] = d1 * rstd * g[threadIdx.x + 256] + bb[threadIdx.x + 256];
}

// ---------------- causal softmax, in-place, zero-fills masked tail ----------------
__global__ void softmax_causal_k(float* __restrict__ attn) {
    long long z = blockIdx.y;
    int t = blockIdx.x;
    float* row = attn + z * (long long)(T_*T_) + (long long)t * T_;
    int len = t + 1;
    float mx = -1e30f;
    for (int s = threadIdx.x; s < len; s += 256) mx = fmaxf(mx, row[s]);
    mx = blockReduceMax(mx);
    float sum = 0.f;
    for (int s = threadIdx.x; s < len; s += 256) sum += expf(row[s] - mx);
    sum = blockReduceSum(sum);
    float inv = 1.f / sum;
    for (int s = threadIdx.x; s < len; s += 256) row[s] = expf(row[s] - mx) * inv;
    for (int s = len + threadIdx.x; s < T_; s += 256) row[s] = 0.f;
}

// ---------------- generic batched SGEMM ----------------
// C[z] = alpha * A[z] @ op(B[z]) (+ bias) (+ resid) (relu?)
// A: M x K (lda), B: K x N (ldb) or N x K if TRANSB, C: M x N (ldc).
// Batch z decomposed as (zo, zi) with zi = z % innerCnt; offsets zo*so + zi*si.
#define BM 64
#define BN 64
#define BKK 16

template<bool TRANSB, bool RELU, bool HASBIAS, bool HASRES, bool CAUSAL>
__global__ __launch_bounds__(256)
void gemm_k(const float* __restrict__ A, const float* __restrict__ Bm,
            float* __restrict__ C,
            int M, int N, int K, int lda, int ldb, int ldc,
            int innerCnt,
            long long soA, long long siA,
            long long soB, long long siB,
            long long soC, long long siC,
            const float* __restrict__ bias,
            const float* __restrict__ resid,
            float alpha) {
    int row0 = blockIdx.y * BM;
    int col0 = blockIdx.x * BN;
    if (CAUSAL) {
        if (col0 > row0 + BM - 1) return;   // tile entirely above diagonal
    }
    int bz = blockIdx.z;
    int zo = bz / innerCnt;
    int zi = bz - zo * innerCnt;
    A  += zo * soA + zi * siA;
    Bm += zo * soB + zi * siB;
    C  += zo * soC + zi * siC;
    const float* R = resid;
    if (HASRES) R += zo * soC + zi * siC;

    __shared__ float As[BKK][BM];
    __shared__ float Bs[BKK][BN + 4];

    int tid = threadIdx.x;
    int tx = tid & 15;        // n group
    int ty = tid >> 4;        // m group
    float acc[4][4] = {};

    for (int k0 = 0; k0 < K; k0 += BKK) {
        // A tile: 64 rows x 16 k
        #pragma unroll
        for (int i = 0; i < 4; i++) {
            int li = tid * 4 + i;
            int m = li >> 4, k = li & 15;
            int gm = row0 + m, gk = k0 + k;
            float v = 0.f;
            if (gm < M && gk < K) v = A[(long long)gm * lda + gk];
            As[k][m] = v;
        }
        // B tile
        if (!TRANSB) {
            #pragma unroll
            for (int i = 0; i < 4; i++) {
                int li = tid * 4 + i;
                int k = li >> 6, n = li & 63;
                int gk = k0 + k, gn = col0 + n;
                float v = 0.f;
                if (gk < K && gn < N) v = Bm[(long long)gk * ldb + gn];
                Bs[k][n] = v;
            }
        } else {
            #pragma unroll
            for (int i = 0; i < 4; i++) {
                int li = tid * 4 + i;
                int n = li >> 4, k = li & 15;
                int gn = col0 + n, gk = k0 + k;
                float v = 0.f;
                if (gn < N && gk < K) v = Bm[(long long)gn * ldb + gk];
                Bs[k][n] = v;
            }
        }
        __syncthreads();
        #pragma unroll
        for (int k = 0; k < BKK; k++) {
            float4 a4 = *(const float4*)&As[k][ty * 4];
            float4 b4 = *(const float4*)&Bs[k][tx * 4];
            float a[4] = {a4.x, a4.y, a4.z, a4.w};
            float b[4] = {b4.x, b4.y, b4.z, b4.w};
            #pragma unroll
            for (int i = 0; i < 4; i++)
                #pragma unroll
                for (int j = 0; j < 4; j++)
                    acc[i][j] = fmaf(a[i], b[j], acc[i][j]);
        }
        __syncthreads();
    }

    #pragma unroll
    for (int i = 0; i < 4; i++) {
        int gm = row0 + ty * 4 + i;
        if (gm >= M) continue;
        #pragma unroll
        for (int j = 0; j < 4; j++) {
            int gn = col0 + tx * 4 + j;
            if (gn >= N) continue;
            float v = acc[i][j] * alpha;
            if (HASBIAS) v += bias[gn];
            if (HASRES)  v += R[(long long)gm * ldc + gn];
            if (RELU)    v = fmaxf(v, 0.f);
            C[(long long)gm * ldc + gn] = v;
        }
    }
}

// ---------------- host launcher ----------------
extern "C" void kernel_launch(void* const* d_in, const int* in_sizes, int n_in,
                              void* d_out, int out_size) {
    const int*   idx   = (const int*)  d_in[0];
    const float* tok   = (const float*)d_in[1];
    const float* pos   = (const float*)d_in[2];
    const float* ln1_g = (const float*)d_in[3];
    const float* ln1_b = (const float*)d_in[4];
    const float* Wq    = (const float*)d_in[5];
    const float* Wk    = (const float*)d_in[6];
    const float* Wv    = (const float*)d_in[7];
    const float* Wo    = (const float*)d_in[8];
    const float* bo    = (const float*)d_in[9];
    const float* ln2_g = (const float*)d_in[10];
    const float* ln2_b = (const float*)d_in[11];
    const float* W1    = (const float*)d_in[12];
    const float* b1    = (const float*)d_in[13];
    const float* W2    = (const float*)d_in[14];
    const float* b2    = (const float*)d_in[15];
    const float* lnf_g = (const float*)d_in[16];
    const float* lnf_b = (const float*)d_in[17];
    const float* Wlm   = (const float*)d_in[18];

    float* out    = (float*)d_out;
    float* logits = out;                                  // (B,T,V)
    float* attn   = out + (long long)B_*T_*V_;            // (L,B,H,T,T)
    const long long ATTN1 = (long long)B_*H_*T_*T_;

    float *x, *h, *q, *k, *v, *y, *m;
    cudaGetSymbolAddress((void**)&x, g_x);
    cudaGetSymbolAddress((void**)&h, g_h);
    cudaGetSymbolAddress((void**)&q, g_q);
    cudaGetSymbolAddress((void**)&k, g_k);
    cudaGetSymbolAddress((void**)&v, g_v);
    cudaGetSymbolAddress((void**)&y, g_y);
    cudaGetSymbolAddress((void**)&m, g_m);

    // 1. embedding
    {
        int n = BT_*E_;
        embed_k<<<(n + 255) / 256, 256>>>(idx, tok, pos, x);
    }

    dim3 gE(E_ / 64, BT_ / 64);                 // (8, 64)    E-output GEMMs
    dim3 gS(T_ / 64, T_ / 64, B_*H_);           // (16,16,32) scores
    dim3 gAV(1, T_ / 64, B_*H_);                // (1, 16,32) attn @ V
    dim3 gM1((HID_ + 63) / 64, BT_ / 64);       // (2, 64)    mlp1
    dim3 gLM(V_ / 64, BT_ / 64);                // (500,64)   lm head
    const float scale = 0.125f;                 // 1/sqrt(64)

    for (int l = 0; l < L_; l++) {
        float* attnL = attn + (long long)l * ATTN1;

        layernorm_k<<<BT_, 256>>>(x, ln1_g + l*E_, ln1_b + l*E_, h);

        // q/k/v = h @ W
        gemm_k<false,false,false,false,false><<<gE, 256>>>(
            h, Wq + (long long)l*E_*E_, q, BT_, E_, E_, E_, E_, E_,
            1, 0,0, 0,0, 0,0, nullptr, nullptr, 1.f);
        gemm_k<false,false,false,false,false><<<gE, 256>>>(
            h, Wk + (long long)l*E_*E_, k, BT_, E_, E_, E_, E_, E_,
            1, 0,0, 0,0, 0,0, nullptr, nullptr, 1.f);
        gemm_k<false,false,false,false,false><<<gE, 256>>>(
            h, Wv + (long long)l*E_*E_, v, BT_, E_, E_, E_, E_, E_,
            1, 0,0, 0,0, 0,0, nullptr, nullptr, 1.f);

        // scores = scale * Q @ K^T  (batched over b,h; causal tiles skipped)
        gemm_k<true,false,false,false,true><<<gS, 256>>>(
            q, k, attnL, T_, T_, HD_, E_, E_, T_,
            H_,
            (long long)T_*E_, (long long)HD_,      // A (q): b-stride, h-stride
            (long long)T_*E_, (long long)HD_,      // B (k)
            (long long)H_*T_*T_, (long long)T_*T_, // C (attn)
            nullptr, nullptr, scale);

        softmax_causal_k<<<dim3(T_, B_*H_), 256>>>(attnL);

        // y = P @ V
        gemm_k<false,false,false,false,false><<<gAV, 256>>>(
            attnL, v, y, T_, HD_, T_, T_, E_, E_,
            H_,
            (long long)H_*T_*T_, (long long)T_*T_, // A (attn)
            (long long)T_*E_, (long long)HD_,      // B (v)
            (long long)T_*E_, (long long)HD_,      // C (y in (b,t,h,d) layout)
            nullptr, nullptr, 1.f);

        // x = x + y @ Wo + bo
        gemm_k<false,false,true,true,false><<<gE, 256>>>(
            y, Wo + (long long)l*E_*E_, x, BT_, E_, E_, E_, E_, E_,
            1, 0,0, 0,0, 0,0, bo + l*E_, x, 1.f);

        layernorm_k<<<BT_, 256>>>(x, ln2_g + l*E_, ln2_b + l*E_, h);

        // m = relu(h @ W1 + b1)
        gemm_k<false,true,true,false,false><<<gM1, 256>>>(
            h, W1 + (long long)l*E_*HID_, m, BT_, HID_, E_, E_, HID_, HID_,
            1, 0,0, 0,0, 0,0, b1 + l*HID_, nullptr, 1.f);

        // x = x + m @ W2 + b2
        gemm_k<false,false,true,true,false><<<gE, 256>>>(
            m, W2 + (long long)l*HID_*E_, x, BT_, E_, HID_, HID_, E_, E_,
            1, 0,0, 0,0, 0,0, b2 + l*E_, x, 1.f);
    }

    // final LN + LM head
    layernorm_k<<<BT_, 256>>>(x, lnf_g, lnf_b, h);
    gemm_k<false,false,false,false,false><<<gLM, 256>>>(
        h, Wlm, logits, BT_, V_, E_, E_, V_, V_,
        1, 0,0, 0,0, 0,0, nullptr, nullptr, 1.f);
}

// round 2
// speedup vs baseline: 1.0014x; 1.0014x over previous
#include <cuda_runtime.h>

// Problem constants
#define B_   4
#define T_   1024
#define E_   512
#define H_   8
#define L_   4
#define V_   32000
#define HID_ 100
#define HD_  64
#define BT_  (B_*T_)

// ---------------- scratch (no allocations allowed) ----------------
__device__ float g_x[BT_*E_];
__device__ float g_h[BT_*E_];
__device__ float g_q[BT_*E_];
__device__ float g_k[BT_*E_];
__device__ float g_v[BT_*E_];
__device__ float g_y[BT_*E_];
__device__ float g_m[BT_*HID_];

// ---------------- block reductions ----------------
__device__ __forceinline__ float blockReduceSum(float v) {
    __shared__ float sh[32];
    int lane = threadIdx.x & 31, w = threadIdx.x >> 5;
    #pragma unroll
    for (int o = 16; o > 0; o >>= 1) v += __shfl_xor_sync(0xffffffffu, v, o);
    if (lane == 0) sh[w] = v;
    __syncthreads();
    v = (threadIdx.x < (blockDim.x >> 5)) ? sh[threadIdx.x] : 0.f;
    if (w == 0) {
        #pragma unroll
        for (int o = 16; o > 0; o >>= 1) v += __shfl_xor_sync(0xffffffffu, v, o);
        if (lane == 0) sh[0] = v;
    }
    __syncthreads();
    float r = sh[0];
    __syncthreads();
    return r;
}

__device__ __forceinline__ float blockReduceMax(float v) {
    __shared__ float sh[32];
    int lane = threadIdx.x & 31, w = threadIdx.x >> 5;
    #pragma unroll
    for (int o = 16; o > 0; o >>= 1) v = fmaxf(v, __shfl_xor_sync(0xffffffffu, v, o));
    if (lane == 0) sh[w] = v;
    __syncthreads();
    v = (threadIdx.x < (blockDim.x >> 5)) ? sh[threadIdx.x] : -1e30f;
    if (w == 0) {
        #pragma unroll
        for (int o = 16; o > 0; o >>= 1) v = fmaxf(v, __shfl_xor_sync(0xffffffffu, v, o));
        if (lane == 0) sh[0] = v;
    }
    __syncthreads();
    float r = sh[0];
    __syncthreads();
    return r;
}

// ---------------- embedding ----------------
__global__ void embed_k(const int* __restrict__ idx, const float* __restrict__ tok,
                        const float* __restrict__ pos, float* __restrict__ x) {
    int i = blockIdx.x * 256 + threadIdx.x;
    if (i >= BT_*E_) return;
    int e  = i & (E_-1);
    int bt = i >> 9;          // /E_
    int t  = bt & (T_-1);
    x[i] = tok[(long long)idx[bt]*E_ + e] + pos[t*E_ + e];
}

// ---------------- layernorm (one block per row, 256 threads, E=512) ----------------
__global__ void layernorm_k(const float* __restrict__ x, const float* __restrict__ g,
                            const float* __restrict__ bb, float* __restrict__ out) {
    const float* xr = x + (long long)blockIdx.x * E_;
    float v0 = xr[threadIdx.x], v1 = xr[threadIdx.x + 256];
    float mean = blockReduceSum(v0 + v1) * (1.f / E_);
    float d0 = v0 - mean, d1 = v1 - mean;
    float var = blockReduceSum(d0*d0 + d1*d1) * (1.f / E_);
    float rstd = rsqrtf(var + 1e-5f);
    float* o = out + (long long)blockIdx.x * E_;
    o[threadIdx.x]       = d0 * rstd * g[threadIdx.x]       + bb[threadIdx.x];
    o[threadIdx.x + 256] = d1 * rstd * g[threadIdx.x + 256] + bb[threadIdx.x + 256];
}

// ---------------- causal softmax, in-place, zero-fills masked tail ----------------
__global__ void softmax_causal_k(float* __restrict__ attn) {
    long long z = blockIdx.y;
    int t = blockIdx.x;
    float* row = attn + z * (long long)(T_*T_) + (long long)t * T_;
    int len = t + 1;
    float mx = -1e30f;
    for (int s = threadIdx.x; s < len; s += 256) mx = fmaxf(mx, row[s]);
    mx = blockReduceMax(mx);
    float sum = 0.f;
    for (int s = threadIdx.x; s < len; s += 256) sum += expf(row[s] - mx);
    sum = blockReduceSum(sum);
    float inv = 1.f / sum;
    for (int s = threadIdx.x; s < len; s += 256) row[s] = expf(row[s] - mx) * inv;
    for (int s = len + threadIdx.x; s < T_; s += 256) row[s] = 0.f;
}

// ---------------- generic batched SGEMM ----------------
// C[z] = alpha * A[z] @ op(B[z]) (+ bias) (+ resid) (relu?)
// A: M x K (lda), B: K x N (ldb) or N x K if TRANSB, C: M x N (ldc).
// Batch z decomposed as (zo, zi) with zi = z % innerCnt; offsets zo*so + zi*si.
#define BM 64
#define BN 64
#define BKK 16

template<bool TRANSB, bool RELU, bool HASBIAS, bool HASRES, bool CAUSAL>
__global__ __launch_bounds__(256)
void gemm_k(const float* __restrict__ A, const float* __restrict__ Bm,
            float* __restrict__ C,
            int M, int N, int K, int lda, int ldb, int ldc,
            int innerCnt,
            long long soA, long long siA,
            long long soB, long long siB,
            long long soC, long long siC,
            const float* __restrict__ bias,
            const float* __restrict__ resid,
            float alpha) {
    int row0 = blockIdx.y * BM;
    int col0 = blockIdx.x * BN;
    if (CAUSAL) {
        if (col0 > row0 + BM - 1) return;   // tile entirely above diagonal
    }
    int bz = blockIdx.z;
    int zo = bz / innerCnt;
    int zi = bz - zo * innerCnt;
    A  += zo * soA + zi * siA;
    Bm += zo * soB + zi * siB;
    C  += zo * soC + zi * siC;
    const float* R = resid;
    if (HASRES) R += zo * soC + zi * siC;

    __shared__ float As[BKK][BM];
    __shared__ float Bs[BKK][BN + 4];

    int tid = threadIdx.x;
    int tx = tid & 15;        // n group
    int ty = tid >> 4;        // m group
    float acc[4][4] = {};

    for (int k0 = 0; k0 < K; k0 += BKK) {
        // A tile: 64 rows x 16 k
        #pragma unroll
        for (int i = 0; i < 4; i++) {
            int li = tid * 4 + i;
            int m = li >> 4, k = li & 15;
            int gm = row0 + m, gk = k0 + k;
            float v = 0.f;
            if (gm < M && gk < K) v = A[(long long)gm * lda + gk];
            As[k][m] = v;
        }
        // B tile
        if (!TRANSB) {
            #pragma unroll
            for (int i = 0; i < 4; i++) {
                int li = tid * 4 + i;
                int k = li >> 6, n = li & 63;
                int gk = k0 + k, gn = col0 + n;
                float v = 0.f;
                if (gk < K && gn < N) v = Bm[(long long)gk * ldb + gn];
                Bs[k][n] = v;
            }
        } else {
            #pragma unroll
            for (int i = 0; i < 4; i++) {
                int li = tid * 4 + i;
                int n = li >> 4, k = li & 15;
                int gn = col0 + n, gk = k0 + k;
                float v = 0.f;
                if (gn < N && gk < K) v = Bm[(long long)gn * ldb + gk];
                Bs[k][n] = v;
            }
        }
        __syncthreads();
        #pragma unroll
        for (int k = 0; k < BKK; k++) {
            float4 a4 = *(const float4*)&As[k][ty * 4];
            float4 b4 = *(const float4*)&Bs[k][tx * 4];
            float a[4] = {a4.x, a4.y, a4.z, a4.w};
            float b[4] = {b4.x, b4.y, b4.z, b4.w};
            #pragma unroll
            for (int i = 0; i < 4; i++)
                #pragma unroll
                for (int j = 0; j < 4; j++)
                    acc[i][j] = fmaf(a[i], b[j], acc[i][j]);
        }
        __syncthreads();
    }

    #pragma unroll
    for (int i = 0; i < 4; i++) {
        int gm = row0 + ty * 4 + i;
        if (gm >= M) continue;
        #pragma unroll
        for (int j = 0; j < 4; j++) {
            int gn = col0 + tx * 4 + j;
            if (gn >= N) continue;
            float v = acc[i][j] * alpha;
            if (HASBIAS) v += bias[gn];
            if (HASRES)  v += R[(long long)gm * ldc + gn];
            if (RELU)    v = fmaxf(v, 0.f);
            C[(long long)gm * ldc + gn] = v;
        }
    }
}

// ---------------- host launcher ----------------
extern "C" void kernel_launch(void* const* d_in, const int* in_sizes, int n_in,
                              void* d_out, int out_size) {
    const int*   idx   = (const int*)  d_in[0];
    const float* tok   = (const float*)d_in[1];
    const float* pos   = (const float*)d_in[2];
    const float* ln1_g = (const float*)d_in[3];
    const float* ln1_b = (const float*)d_in[4];
    const float* Wq    = (const float*)d_in[5];
    const float* Wk    = (const float*)d_in[6];
    const float* Wv    = (const float*)d_in[7];
    const float* Wo    = (const float*)d_in[8];
    const float* bo    = (const float*)d_in[9];
    const float* ln2_g = (const float*)d_in[10];
    const float* ln2_b = (const float*)d_in[11];
    const float* W1    = (const float*)d_in[12];
    const float* b1    = (const float*)d_in[13];
    const float* W2    = (const float*)d_in[14];
    const float* b2    = (const float*)d_in[15];
    const float* lnf_g = (const float*)d_in[16];
    const float* lnf_b = (const float*)d_in[17];
    const float* Wlm   = (const float*)d_in[18];

    float* out    = (float*)d_out;
    float* logits = out;                                  // (B,T,V)
    float* attn   = out + (long long)B_*T_*V_;            // (L,B,H,T,T)
    const long long ATTN1 = (long long)B_*H_*T_*T_;

    float *x, *h, *q, *k, *v, *y, *m;
    cudaGetSymbolAddress((void**)&x, g_x);
    cudaGetSymbolAddress((void**)&h, g_h);
    cudaGetSymbolAddress((void**)&q, g_q);
    cudaGetSymbolAddress((void**)&k, g_k);
    cudaGetSymbolAddress((void**)&v, g_v);
    cudaGetSymbolAddress((void**)&y, g_y);
    cudaGetSymbolAddress((void**)&m, g_m);

    // 1. embedding
    {
        int n = BT_*E_;
        embed_k<<<(n + 255) / 256, 256>>>(idx, tok, pos, x);
    }

    dim3 gE(E_ / 64, BT_ / 64);                 // (8, 64)    E-output GEMMs
    dim3 gS(T_ / 64, T_ / 64, B_*H_);           // (16,16,32) scores
    dim3 gAV(1, T_ / 64, B_*H_);                // (1, 16,32) attn @ V
    dim3 gM1((HID_ + 63) / 64, BT_ / 64);       // (2, 64)    mlp1
    dim3 gLM(V_ / 64, BT_ / 64);                // (500,64)   lm head
    const float scale = 0.125f;                 // 1/sqrt(64)

    for (int l = 0; l < L_; l++) {
        float* attnL = attn + (long long)l * ATTN1;

        layernorm_k<<<BT_, 256>>>(x, ln1_g + l*E_, ln1_b + l*E_, h);

        // q/k/v = h @ W
        gemm_k<false,false,false,false,false><<<gE, 256>>>(
            h, Wq + (long long)l*E_*E_, q, BT_, E_, E_, E_, E_, E_,
            1, 0,0, 0,0, 0,0, nullptr, nullptr, 1.f);
        gemm_k<false,false,false,false,false><<<gE, 256>>>(
            h, Wk + (long long)l*E_*E_, k, BT_, E_, E_, E_, E_, E_,
            1, 0,0, 0,0, 0,0, nullptr, nullptr, 1.f);
        gemm_k<false,false,false,false,false><<<gE, 256>>>(
            h, Wv + (long long)l*E_*E_, v, BT_, E_, E_, E_, E_, E_,
            1, 0,0, 0,0, 0,0, nullptr, nullptr, 1.f);

        // scores = scale * Q @ K^T  (batched over b,h; causal tiles skipped)
        gemm_k<true,false,false,false,true><<<gS, 256>>>(
            q, k, attnL, T_, T_, HD_, E_, E_, T_,
            H_,
            (long long)T_*E_, (long long)HD_,      // A (q): b-stride, h-stride
            (long long)T_*E_, (long long)HD_,      // B (k)
            (long long)H_*T_*T_, (long long)T_*T_, // C (attn)
            nullptr, nullptr, scale);

        softmax_causal_k<<<dim3(T_, B_*H_), 256>>>(attnL);

        // y = P @ V
        gemm_k<false,false,false,false,false><<<gAV, 256>>>(
            attnL, v, y, T_, HD_, T_, T_, E_, E_,
            H_,
            (long long)H_*T_*T_, (long long)T_*T_, // A (attn)
            (long long)T_*E_, (long long)HD_,      // B (v)
            (long long)T_*E_, (long long)HD_,      // C (y in (b,t,h,d) layout)
            nullptr, nullptr, 1.f);

        // x = x + y @ Wo + bo
        gemm_k<false,false,true,true,false><<<gE, 256>>>(
            y, Wo + (long long)l*E_*E_, x, BT_, E_, E_, E_, E_, E_,
            1, 0,0, 0,0, 0,0, bo + l*E_, x, 1.f);

        layernorm_k<<<BT_, 256>>>(x, ln2_g + l*E_, ln2_b + l*E_, h);

        // m = relu(h @ W1 + b1)
        gemm_k<false,true,true,false,false><<<gM1, 256>>>(
            h, W1 + (long long)l*E_*HID_, m, BT_, HID_, E_, E_, HID_, HID_,
            1, 0,0, 0,0, 0,0, b1 + l*HID_, nullptr, 1.f);

        // x = x + m @ W2 + b2
        gemm_k<false,false,true,true,false><<<gE, 256>>>(
            m, W2 + (long long)l*HID_*E_, x, BT_, E_, HID_, HID_, E_, E_,
            1, 0,0, 0,0, 0,0, b2 + l*E_, x, 1.f);
    }

    // final LN + LM head
    layernorm_k<<<BT_, 256>>>(x, lnf_g, lnf_b, h);
    gemm_k<false,false,false,false,false><<<gLM, 256>>>(
        h, Wlm, logits, BT_, V_, E_, E_, V_, V_,
        1, 0,0, 0,0, 0,0, nullptr, nullptr, 1.f);
}

// round 3
// speedup vs baseline: 1.6153x; 1.6130x over previous
#include <cuda_runtime.h>

// Problem constants
#define B_   4
#define T_   1024
#define E_   512
#define H_   8
#define L_   4
#define V_   32000
#define HID_ 100
#define HD_  64
#define BT_  (B_*T_)

// ---------------- scratch (no allocations allowed) ----------------
__device__ float g_x[BT_*E_];
__device__ float g_h[BT_*E_];
__device__ float g_q[BT_*E_];
__device__ float g_k[BT_*E_];
__device__ float g_v[BT_*E_];
__device__ float g_y[BT_*E_];
__device__ float g_m[BT_*HID_];

// ---------------- block reductions ----------------
__device__ __forceinline__ float blockReduceSum(float v) {
    __shared__ float sh[32];
    int lane = threadIdx.x & 31, w = threadIdx.x >> 5;
    #pragma unroll
    for (int o = 16; o > 0; o >>= 1) v += __shfl_xor_sync(0xffffffffu, v, o);
    if (lane == 0) sh[w] = v;
    __syncthreads();
    v = (threadIdx.x < (blockDim.x >> 5)) ? sh[threadIdx.x] : 0.f;
    if (w == 0) {
        #pragma unroll
        for (int o = 16; o > 0; o >>= 1) v += __shfl_xor_sync(0xffffffffu, v, o);
        if (lane == 0) sh[0] = v;
    }
    __syncthreads();
    float r = sh[0];
    __syncthreads();
    return r;
}

__device__ __forceinline__ float blockReduceMax(float v) {
    __shared__ float sh[32];
    int lane = threadIdx.x & 31, w = threadIdx.x >> 5;
    #pragma unroll
    for (int o = 16; o > 0; o >>= 1) v = fmaxf(v, __shfl_xor_sync(0xffffffffu, v, o));
    if (lane == 0) sh[w] = v;
    __syncthreads();
    v = (threadIdx.x < (blockDim.x >> 5)) ? sh[threadIdx.x] : -1e30f;
    if (w == 0) {
        #pragma unroll
        for (int o = 16; o > 0; o >>= 1) v = fmaxf(v, __shfl_xor_sync(0xffffffffu, v, o));
        if (lane == 0) sh[0] = v;
    }
    __syncthreads();
    float r = sh[0];
    __syncthreads();
    return r;
}

// ---------------- embedding ----------------
__global__ void embed_k(const int* __restrict__ idx, const float* __restrict__ tok,
                        const float* __restrict__ pos, float* __restrict__ x) {
    int i = blockIdx.x * 256 + threadIdx.x;
    if (i >= BT_*E_) return;
    int e  = i & (E_-1);
    int bt = i >> 9;          // /E_
    int t  = bt & (T_-1);
    x[i] = tok[(long long)idx[bt]*E_ + e] + pos[t*E_ + e];
}

// ---------------- layernorm (one block per row, 256 threads, E=512) ----------------
__global__ void layernorm_k(const float* __restrict__ x, const float* __restrict__ g,
                            const float* __restrict__ bb, float* __restrict__ out) {
    const float* xr = x + (long long)blockIdx.x * E_;
    float v0 = xr[threadIdx.x], v1 = xr[threadIdx.x + 256];
    float mean = blockReduceSum(v0 + v1) * (1.f / E_);
    float d0 = v0 - mean, d1 = v1 - mean;
    float var = blockReduceSum(d0*d0 + d1*d1) * (1.f / E_);
    float rstd = rsqrtf(var + 1e-5f);
    float* o = out + (long long)blockIdx.x * E_;
    o[threadIdx.x]       = d0 * rstd * g[threadIdx.x]       + bb[threadIdx.x];
    o[threadIdx.x + 256] = d1 * rstd * g[threadIdx.x + 256] + bb[threadIdx.x + 256];
}

// ---------------- causal softmax, in-place, zero-fills masked tail ----------------
__global__ void softmax_causal_k(float* __restrict__ attn) {
    long long z = blockIdx.y;
    int t = blockIdx.x;
    float* row = attn + z * (long long)(T_*T_) + (long long)t * T_;
    int len = t + 1;
    float mx = -1e30f;
    for (int s = threadIdx.x; s < len; s += 256) mx = fmaxf(mx, row[s]);
    mx = blockReduceMax(mx);
    float sum = 0.f;
    for (int s = threadIdx.x; s < len; s += 256) sum += expf(row[s] - mx);
    sum = blockReduceSum(sum);
    float inv = 1.f / sum;
    for (int s = threadIdx.x; s < len; s += 256) row[s] = expf(row[s] - mx) * inv;
    for (int s = len + threadIdx.x; s < T_; s += 256) row[s] = 0.f;
}

// ============================================================================
// Fast dense SGEMM: 128x128 tile, BK=8, 256 threads, 8x8 per thread,
// double-buffered shared memory, float4 everywhere.
// Requires M%128==0, N%128==0, K%8==0. C = A@B (+bias) (+resid)
// ============================================================================
template<bool HASBIAS, bool HASRES>
__global__ __launch_bounds__(256, 2)
void gemm128_k(const float* __restrict__ A, const float* __restrict__ Bm,
               float* __restrict__ C, int M, int N, int K,
               int lda, int ldb, int ldc,
               const float* __restrict__ bias,
               const float* __restrict__ resid) {
    __shared__ float As[2][8][128];
    __shared__ float Bs[2][8][128];

    const int tid  = threadIdx.x;
    const int tx   = tid & 15;          // 0..15 (col group)
    const int ty   = tid >> 4;          // 0..15 (row group)
    const int row0 = blockIdx.y * 128;
    const int col0 = blockIdx.x * 128;

    // global load addressing
    const int ar = tid >> 1;            // 0..127 row in A tile
    const int ac = (tid & 1) * 4;       // 0 or 4  (k offset)
    const int br = tid >> 5;            // 0..7   k row in B tile
    const int bc = (tid & 31) * 4;      // 0..124 col in B tile

    const float* Ap = A + (long long)(row0 + ar) * lda + ac;
    const float* Bp = Bm + (long long)br * ldb + col0 + bc;

    float acc[8][8];
    #pragma unroll
    for (int i = 0; i < 8; i++)
        #pragma unroll
        for (int j = 0; j < 8; j++) acc[i][j] = 0.f;

    const int KT = K >> 3;

    // prologue: load tile 0
    {
        float4 av = *(const float4*)Ap;
        As[0][ac + 0][ar] = av.x;
        As[0][ac + 1][ar] = av.y;
        As[0][ac + 2][ar] = av.z;
        As[0][ac + 3][ar] = av.w;
        *(float4*)&Bs[0][br][bc] = *(const float4*)Bp;
    }
    __syncthreads();

    for (int kt = 0; kt < KT; kt++) {
        const int buf = kt & 1;
        float4 av, bv;
        if (kt + 1 < KT) {
            av = *(const float4*)(Ap + (kt + 1) * 8);
            bv = *(const float4*)(Bp + (long long)(kt + 1) * 8 * ldb);
        }
        #pragma unroll
        for (int k = 0; k < 8; k++) {
            float4 a0 = *(const float4*)&As[buf][k][ty * 4];
            float4 a1 = *(const float4*)&As[buf][k][ty * 4 + 64];
            float4 b0 = *(const float4*)&Bs[buf][k][tx * 4];
            float4 b1 = *(const float4*)&Bs[buf][k][tx * 4 + 64];
            float a[8] = {a0.x, a0.y, a0.z, a0.w, a1.x, a1.y, a1.z, a1.w};
            float b[8] = {b0.x, b0.y, b0.z, b0.w, b1.x, b1.y, b1.z, b1.w};
            #pragma unroll
            for (int i = 0; i < 8; i++)
                #pragma unroll
                for (int j = 0; j < 8; j++)
                    acc[i][j] = fmaf(a[i], b[j], acc[i][j]);
        }
        if (kt + 1 < KT) {
            const int nb = 1 - buf;
            As[nb][ac + 0][ar] = av.x;
            As[nb][ac + 1][ar] = av.y;
            As[nb][ac + 2][ar] = av.z;
            As[nb][ac + 3][ar] = av.w;
            *(float4*)&Bs[nb][br][bc] = bv;
            __syncthreads();
        }
    }

    // epilogue: 2x2 quadrants of 4x4, float4 stores
    #pragma unroll
    for (int hi = 0; hi < 2; hi++) {
        #pragma unroll
        for (int i = 0; i < 4; i++) {
            const int gm = row0 + hi * 64 + ty * 4 + i;
            float* crow = C + (long long)gm * ldc;
            const float* rrow = HASRES ? (resid + (long long)gm * ldc) : nullptr;
            #pragma unroll
            for (int hj = 0; hj < 2; hj++) {
                const int gn = col0 + hj * 64 + tx * 4;
                float4 v;
                v.x = acc[hi * 4 + i][hj * 4 + 0];
                v.y = acc[hi * 4 + i][hj * 4 + 1];
                v.z = acc[hi * 4 + i][hj * 4 + 2];
                v.w = acc[hi * 4 + i][hj * 4 + 3];
                if (HASBIAS) {
                    float4 bb = *(const float4*)(bias + gn);
                    v.x += bb.x; v.y += bb.y; v.z += bb.z; v.w += bb.w;
                }
                if (HASRES) {
                    float4 rr = *(const float4*)(rrow + gn);
                    v.x += rr.x; v.y += rr.y; v.z += rr.z; v.w += rr.w;
                }
                *(float4*)(crow + gn) = v;
            }
        }
    }
}

// ---------------- generic batched SGEMM (small/odd shapes) ----------------
// C[z] = alpha * A[z] @ op(B[z]) (+ bias) (+ resid) (relu?)
// CAUSAL: skip output tiles fully above diagonal. CAUSALK: K loop only to row0+BM.
#define BM 64
#define BN 64
#define BKK 16

template<bool TRANSB, bool RELU, bool HASBIAS, bool HASRES, bool CAUSAL, bool CAUSALK>
__global__ __launch_bounds__(256)
void gemm_k(const float* __restrict__ A, const float* __restrict__ Bm,
            float* __restrict__ C,
            int M, int N, int K, int lda, int ldb, int ldc,
            int innerCnt,
            long long soA, long long siA,
            long long soB, long long siB,
            long long soC, long long siC,
            const float* __restrict__ bias,
            const float* __restrict__ resid,
            float alpha) {
    int row0 = blockIdx.y * BM;
    int col0 = blockIdx.x * BN;
    if (CAUSAL) {
        if (col0 > row0 + BM - 1) return;   // tile entirely above diagonal
    }
    int bz = blockIdx.z;
    int zo = bz / innerCnt;
    int zi = bz - zo * innerCnt;
    A  += zo * soA + zi * siA;
    Bm += zo * soB + zi * siB;
    C  += zo * soC + zi * siC;
    const float* R = resid;
    if (HASRES) R += zo * soC + zi * siC;

    __shared__ float As[BKK][BM];
    __shared__ float Bs[BKK][BN + 4];

    int tid = threadIdx.x;
    int tx = tid & 15;        // n group
    int ty = tid >> 4;        // m group
    float acc[4][4] = {};

    int Kend = K;
    if (CAUSALK) { int ke = row0 + BM; Kend = ke < K ? ke : K; }

    for (int k0 = 0; k0 < Kend; k0 += BKK) {
        #pragma unroll
        for (int i = 0; i < 4; i++) {
            int li = tid * 4 + i;
            int m = li >> 4, k = li & 15;
            int gm = row0 + m, gk = k0 + k;
            float v = 0.f;
            if (gm < M && gk < K) v = A[(long long)gm * lda + gk];
            As[k][m] = v;
        }
        if (!TRANSB) {
            #pragma unroll
            for (int i = 0; i < 4; i++) {
                int li = tid * 4 + i;
                int k = li >> 6, n = li & 63;
                int gk = k0 + k, gn = col0 + n;
                float v = 0.f;
                if (gk < K && gn < N) v = Bm[(long long)gk * ldb + gn];
                Bs[k][n] = v;
            }
        } else {
            #pragma unroll
            for (int i = 0; i < 4; i++) {
                int li = tid * 4 + i;
                int n = li >> 4, k = li & 15;
                int gn = col0 + n, gk = k0 + k;
                float v = 0.f;
                if (gn < N && gk < K) v = Bm[(long long)gn * ldb + gk];
                Bs[k][n] = v;
            }
        }
        __syncthreads();
        #pragma unroll
        for (int k = 0; k < BKK; k++) {
            float4 a4 = *(const float4*)&As[k][ty * 4];
            float4 b4 = *(const float4*)&Bs[k][tx * 4];
            float a[4] = {a4.x, a4.y, a4.z, a4.w};
            float b[4] = {b4.x, b4.y, b4.z, b4.w};
            #pragma unroll
            for (int i = 0; i < 4; i++)
                #pragma unroll
                for (int j = 0; j < 4; j++)
                    acc[i][j] = fmaf(a[i], b[j], acc[i][j]);
        }
        __syncthreads();
    }

    #pragma unroll
    for (int i = 0; i < 4; i++) {
        int gm = row0 + ty * 4 + i;
        if (gm >= M) continue;
        #pragma unroll
        for (int j = 0; j < 4; j++) {
            int gn = col0 + tx * 4 + j;
            if (gn >= N) continue;
            float v = acc[i][j] * alpha;
            if (HASBIAS) v += bias[gn];
            if (HASRES)  v += R[(long long)gm * ldc + gn];
            if (RELU)    v = fmaxf(v, 0.f);
            C[(long long)gm * ldc + gn] = v;
        }
    }
}

// ---------------- host launcher ----------------
extern "C" void kernel_launch(void* const* d_in, const int* in_sizes, int n_in,
                              void* d_out, int out_size) {
    const int*   idx   = (const int*)  d_in[0];
    const float* tok   = (const float*)d_in[1];
    const float* pos   = (const float*)d_in[2];
    const float* ln1_g = (const float*)d_in[3];
    const float* ln1_b = (const float*)d_in[4];
    const float* Wq    = (const float*)d_in[5];
    const float* Wk    = (const float*)d_in[6];
    const float* Wv    = (const float*)d_in[7];
    const float* Wo    = (const float*)d_in[8];
    const float* bo    = (const float*)d_in[9];
    const float* ln2_g = (const float*)d_in[10];
    const float* ln2_b = (const float*)d_in[11];
    const float* W1    = (const float*)d_in[12];
    const float* b1    = (const float*)d_in[13];
    const float* W2    = (const float*)d_in[14];
    const float* b2    = (const float*)d_in[15];
    const float* lnf_g = (const float*)d_in[16];
    const float* lnf_b = (const float*)d_in[17];
    const float* Wlm   = (const float*)d_in[18];

    float* out    = (float*)d_out;
    float* logits = out;                                  // (B,T,V)
    float* attn   = out + (long long)B_*T_*V_;            // (L,B,H,T,T)
    const long long ATTN1 = (long long)B_*H_*T_*T_;

    float *x, *h, *q, *k, *v, *y, *m;
    cudaGetSymbolAddress((void**)&x, g_x);
    cudaGetSymbolAddress((void**)&h, g_h);
    cudaGetSymbolAddress((void**)&q, g_q);
    cudaGetSymbolAddress((void**)&k, g_k);
    cudaGetSymbolAddress((void**)&v, g_v);
    cudaGetSymbolAddress((void**)&y, g_y);
    cudaGetSymbolAddress((void**)&m, g_m);

    // 1. embedding
    {
        int n = BT_*E_;
        embed_k<<<(n + 255) / 256, 256>>>(idx, tok, pos, x);
    }

    dim3 gE128(E_ / 128, BT_ / 128);            // (4, 32)    QKV / proj
    dim3 gLM128(V_ / 128, BT_ / 128);           // (250, 32)  lm head
    dim3 gS(T_ / 64, T_ / 64, B_*H_);           // (16,16,32) scores
    dim3 gAV(1, T_ / 64, B_*H_);                // (1, 16,32) attn @ V
    dim3 gM1((HID_ + 63) / 64, BT_ / 64);       // (2, 64)    mlp1
    const float scale = 0.125f;                 // 1/sqrt(64)

    for (int l = 0; l < L_; l++) {
        float* attnL = attn + (long long)l * ATTN1;

        layernorm_k<<<BT_, 256>>>(x, ln1_g + l*E_, ln1_b + l*E_, h);

        // q/k/v = h @ W   (fast path)
        gemm128_k<false,false><<<gE128, 256>>>(
            h, Wq + (long long)l*E_*E_, q, BT_, E_, E_, E_, E_, E_, nullptr, nullptr);
        gemm128_k<false,false><<<gE128, 256>>>(
            h, Wk + (long long)l*E_*E_, k, BT_, E_, E_, E_, E_, E_, nullptr, nullptr);
        gemm128_k<false,false><<<gE128, 256>>>(
            h, Wv + (long long)l*E_*E_, v, BT_, E_, E_, E_, E_, E_, nullptr, nullptr);

        // scores = scale * Q @ K^T  (batched over b,h; causal tiles skipped)
        gemm_k<true,false,false,false,true,false><<<gS, 256>>>(
            q, k, attnL, T_, T_, HD_, E_, E_, T_,
            H_,
            (long long)T_*E_, (long long)HD_,
            (long long)T_*E_, (long long)HD_,
            (long long)H_*T_*T_, (long long)T_*T_,
            nullptr, nullptr, scale);

        softmax_causal_k<<<dim3(T_, B_*H_), 256>>>(attnL);

        // y = P @ V  (causal-K: rows only attend to s <= t, tail is zero)
        gemm_k<false,false,false,false,false,true><<<gAV, 256>>>(
            attnL, v, y, T_, HD_, T_, T_, E_, E_,
            H_,
            (long long)H_*T_*T_, (long long)T_*T_,
            (long long)T_*E_, (long long)HD_,
            (long long)T_*E_, (long long)HD_,
            nullptr, nullptr, 1.f);

        // x = x + y @ Wo + bo   (fast path, fused bias+residual)
        gemm128_k<true,true><<<gE128, 256>>>(
            y, Wo + (long long)l*E_*E_, x, BT_, E_, E_, E_, E_, E_, bo + l*E_, x);

        layernorm_k<<<BT_, 256>>>(x, ln2_g + l*E_, ln2_b + l*E_, h);

        // m = relu(h @ W1 + b1)
        gemm_k<false,true,true,false,false,false><<<gM1, 256>>>(
            h, W1 + (long long)l*E_*HID_, m, BT_, HID_, E_, E_, HID_, HID_,
            1, 0,0, 0,0, 0,0, b1 + l*HID_, nullptr, 1.f);

        // x = x + m @ W2 + b2
        gemm_k<false,false,true,true,false,false><<<dim3(E_/64, BT_/64), 256>>>(
            m, W2 + (long long)l*HID_*E_, x, BT_, E_, HID_, HID_, E_, E_,
            1, 0,0, 0,0, 0,0, b2 + l*E_, x, 1.f);
    }

    // final LN + LM head (fast path)
    layernorm_k<<<BT_, 256>>>(x, lnf_g, lnf_b, h);
    gemm128_k<false,false><<<gLM128, 256>>>(
        h, Wlm, logits, BT_, V_, E_, E_, V_, V_, nullptr, nullptr);
}

// round 4
// speedup vs baseline: 2.6497x; 1.6404x over previous
#include <cuda_runtime.h>
#include <cstdint>

// Problem constants
#define B_   4
#define T_   1024
#define E_   512
#define H_   8
#define L_   4
#define V_   32000
#define HID_ 100
#define HD_  64
#define BT_  (B_*T_)

// ---------------- scratch (no allocations allowed) ----------------
__device__ float g_x[BT_*E_];
__device__ float g_h[BT_*E_];
__device__ float g_q[BT_*E_];
__device__ float g_k[BT_*E_];
__device__ float g_v[BT_*E_];
__device__ float g_y[BT_*E_];
__device__ float g_m[BT_*HID_];

// ---------------- block reductions ----------------
__device__ __forceinline__ float blockReduceSum(float v) {
    __shared__ float sh[32];
    int lane = threadIdx.x & 31, w = threadIdx.x >> 5;
    #pragma unroll
    for (int o = 16; o > 0; o >>= 1) v += __shfl_xor_sync(0xffffffffu, v, o);
    if (lane == 0) sh[w] = v;
    __syncthreads();
    v = (threadIdx.x < (blockDim.x >> 5)) ? sh[threadIdx.x] : 0.f;
    if (w == 0) {
        #pragma unroll
        for (int o = 16; o > 0; o >>= 1) v += __shfl_xor_sync(0xffffffffu, v, o);
        if (lane == 0) sh[0] = v;
    }
    __syncthreads();
    float r = sh[0];
    __syncthreads();
    return r;
}

__device__ __forceinline__ float blockReduceMax(float v) {
    __shared__ float sh[32];
    int lane = threadIdx.x & 31, w = threadIdx.x >> 5;
    #pragma unroll
    for (int o = 16; o > 0; o >>= 1) v = fmaxf(v, __shfl_xor_sync(0xffffffffu, v, o));
    if (lane == 0) sh[w] = v;
    __syncthreads();
    v = (threadIdx.x < (blockDim.x >> 5)) ? sh[threadIdx.x] : -1e30f;
    if (w == 0) {
        #pragma unroll
        for (int o = 16; o > 0; o >>= 1) v = fmaxf(v, __shfl_xor_sync(0xffffffffu, v, o));
        if (lane == 0) sh[0] = v;
    }
    __syncthreads();
    float r = sh[0];
    __syncthreads();
    return r;
}

// ---------------- embedding ----------------
__global__ void embed_k(const int* __restrict__ idx, const float* __restrict__ tok,
                        const float* __restrict__ pos, float* __restrict__ x) {
    int i = blockIdx.x * 256 + threadIdx.x;
    if (i >= BT_*E_) return;
    int e  = i & (E_-1);
    int bt = i >> 9;          // /E_
    int t  = bt & (T_-1);
    x[i] = tok[(long long)idx[bt]*E_ + e] + pos[t*E_ + e];
}

// ---------------- layernorm (one block per row, 256 threads, E=512) ----------------
__global__ void layernorm_k(const float* __restrict__ x, const float* __restrict__ g,
                            const float* __restrict__ bb, float* __restrict__ out) {
    const float* xr = x + (long long)blockIdx.x * E_;
    float v0 = xr[threadIdx.x], v1 = xr[threadIdx.x + 256];
    float mean = blockReduceSum(v0 + v1) * (1.f / E_);
    float d0 = v0 - mean, d1 = v1 - mean;
    float var = blockReduceSum(d0*d0 + d1*d1) * (1.f / E_);
    float rstd = rsqrtf(var + 1e-5f);
    float* o = out + (long long)blockIdx.x * E_;
    o[threadIdx.x]       = d0 * rstd * g[threadIdx.x]       + bb[threadIdx.x];
    o[threadIdx.x + 256] = d1 * rstd * g[threadIdx.x + 256] + bb[threadIdx.x + 256];
}

// ---------------- causal softmax, in-place, zero-fills masked tail ----------------
__global__ void softmax_causal_k(float* __restrict__ attn) {
    long long z = blockIdx.y;
    int t = blockIdx.x;
    float* row = attn + z * (long long)(T_*T_) + (long long)t * T_;
    int len = t + 1;
    float mx = -1e30f;
    for (int s = threadIdx.x; s < len; s += 256) mx = fmaxf(mx, row[s]);
    mx = blockReduceMax(mx);
    float sum = 0.f;
    for (int s = threadIdx.x; s < len; s += 256) sum += expf(row[s] - mx);
    sum = blockReduceSum(sum);
    float inv = 1.f / sum;
    for (int s = threadIdx.x; s < len; s += 256) row[s] = expf(row[s] - mx) * inv;
    for (int s = len + threadIdx.x; s < T_; s += 256) row[s] = 0.f;
}

// ============================================================================
// TF32 tensor-core GEMM: 128x128 tile, BK=16, 256 threads (8 warps),
// each warp 64x32 via mma.sync.m16n8k8.tf32. Double-buffered smem.
// Requires M%128==0, N%128==0, K%16==0.
// TRANSB: B is N x K row-major (B[n][k] at Bm[n*ldb+k]).
// CAUSAL: skip tiles fully above diagonal.
// Batched via innerCnt / so,si strides (like gemm_k).
// ============================================================================
__device__ __forceinline__ uint32_t f2tf(float f) {
    uint32_t r;
    asm("cvt.rna.tf32.f32 %0, %1;" : "=r"(r) : "f"(f));
    return r;
}

__device__ __forceinline__ void mma_tf32(float* c, const uint32_t* a, const uint32_t* b) {
    asm volatile(
      "mma.sync.aligned.m16n8k8.row.col.f32.tf32.tf32.f32 "
      "{%0,%1,%2,%3}, {%4,%5,%6,%7}, {%8,%9}, {%0,%1,%2,%3};\n"
      : "+f"(c[0]), "+f"(c[1]), "+f"(c[2]), "+f"(c[3])
      : "r"(a[0]), "r"(a[1]), "r"(a[2]), "r"(a[3]), "r"(b[0]), "r"(b[1]));
}

#define APAD 20    // 128 rows x 20 (k stride)  -> conflict-free frag reads
#define BPAD 136   // 16 k-rows x 136 (n stride)

template<bool TRANSB, bool HASBIAS, bool HASRES, bool CAUSAL>
__global__ __launch_bounds__(256, 2)
void gemm_tf32_k(const float* __restrict__ A, const float* __restrict__ Bm,
                 float* __restrict__ C,
                 int M, int N, int K, int lda, int ldb, int ldc,
                 int innerCnt,
                 long long soA, long long siA,
                 long long soB, long long siB,
                 long long soC, long long siC,
                 const float* __restrict__ bias,
                 const float* __restrict__ resid,
                 float alpha) {
    const int row0 = blockIdx.y * 128;
    const int col0 = blockIdx.x * 128;
    if (CAUSAL && col0 > row0 + 127) return;

    {
        int bz = blockIdx.z;
        int zo = bz / innerCnt;
        int zi = bz - zo * innerCnt;
        A  += zo * soA + zi * siA;
        Bm += zo * soB + zi * siB;
        C  += zo * soC + zi * siC;
        if (HASRES) resid += zo * soC + zi * siC;
    }

    __shared__ uint32_t As[2][128][APAD];
    __shared__ uint32_t Bs[2][16][BPAD];

    const int tid  = threadIdx.x;
    const int lane = tid & 31;
    const int wid  = tid >> 5;
    const int warpM = wid >> 2;          // 0..1  -> 64 rows each
    const int warpN = wid & 3;           // 0..3  -> 32 cols each
    const int g    = lane >> 2;          // group 0..7
    const int tg   = lane & 3;           // thread-in-group 0..3

    // staging addressing
    const int ar = tid >> 1, ac = (tid & 1) * 8;           // A: row, k-offset
    const int bk = tid >> 4, bn = (tid & 15) * 8;          // B (KxN): k-row, n-offset
    const int tnr = tid >> 1, tkc = (tid & 1) * 8;         // B (NxK trans): n-row, k-offset

    float acc[4][4][4];
    #pragma unroll
    for (int i = 0; i < 4; i++)
        #pragma unroll
        for (int j = 0; j < 4; j++)
            #pragma unroll
            for (int r = 0; r < 4; r++) acc[i][j][r] = 0.f;

    const int KT = K >> 4;

    // ---- stage tile 0 ----
    {
        float4 a0 = *(const float4*)(A + (long long)(row0 + ar) * lda + ac);
        float4 a1 = *(const float4*)(A + (long long)(row0 + ar) * lda + ac + 4);
        As[0][ar][ac+0] = f2tf(a0.x); As[0][ar][ac+1] = f2tf(a0.y);
        As[0][ar][ac+2] = f2tf(a0.z); As[0][ar][ac+3] = f2tf(a0.w);
        As[0][ar][ac+4] = f2tf(a1.x); As[0][ar][ac+5] = f2tf(a1.y);
        As[0][ar][ac+6] = f2tf(a1.z); As[0][ar][ac+7] = f2tf(a1.w);
        if (!TRANSB) {
            float4 b0 = *(const float4*)(Bm + (long long)bk * ldb + col0 + bn);
            float4 b1 = *(const float4*)(Bm + (long long)bk * ldb + col0 + bn + 4);
            Bs[0][bk][bn+0] = f2tf(b0.x); Bs[0][bk][bn+1] = f2tf(b0.y);
            Bs[0][bk][bn+2] = f2tf(b0.z); Bs[0][bk][bn+3] = f2tf(b0.w);
            Bs[0][bk][bn+4] = f2tf(b1.x); Bs[0][bk][bn+5] = f2tf(b1.y);
            Bs[0][bk][bn+6] = f2tf(b1.z); Bs[0][bk][bn+7] = f2tf(b1.w);
        } else {
            float4 b0 = *(const float4*)(Bm + (long long)(col0 + tnr) * ldb + tkc);
            float4 b1 = *(const float4*)(Bm + (long long)(col0 + tnr) * ldb + tkc + 4);
            Bs[0][tkc+0][tnr] = f2tf(b0.x); Bs[0][tkc+1][tnr] = f2tf(b0.y);
            Bs[0][tkc+2][tnr] = f2tf(b0.z); Bs[0][tkc+3][tnr] = f2tf(b0.w);
            Bs[0][tkc+4][tnr] = f2tf(b1.x); Bs[0][tkc+5][tnr] = f2tf(b1.y);
            Bs[0][tkc+6][tnr] = f2tf(b1.z); Bs[0][tkc+7][tnr] = f2tf(b1.w);
        }
    }
    __syncthreads();

    for (int kt = 0; kt < KT; kt++) {
        const int buf = kt & 1;
        float4 pa0, pa1, pb0, pb1;
        if (kt + 1 < KT) {
            const int kb = (kt + 1) * 16;
            pa0 = *(const float4*)(A + (long long)(row0 + ar) * lda + kb + ac);
            pa1 = *(const float4*)(A + (long long)(row0 + ar) * lda + kb + ac + 4);
            if (!TRANSB) {
                pb0 = *(const float4*)(Bm + (long long)(kb + bk) * ldb + col0 + bn);
                pb1 = *(const float4*)(Bm + (long long)(kb + bk) * ldb + col0 + bn + 4);
            } else {
                pb0 = *(const float4*)(Bm + (long long)(col0 + tnr) * ldb + kb + tkc);
                pb1 = *(const float4*)(Bm + (long long)(col0 + tnr) * ldb + kb + tkc + 4);
            }
        }

        #pragma unroll
        for (int ks = 0; ks < 2; ks++) {
            const int kb = ks * 8;
            uint32_t af[4][4];
            #pragma unroll
            for (int im = 0; im < 4; im++) {
                const int r = warpM * 64 + im * 16 + g;
                af[im][0] = As[buf][r    ][kb + tg];
                af[im][1] = As[buf][r + 8][kb + tg];
                af[im][2] = As[buf][r    ][kb + tg + 4];
                af[im][3] = As[buf][r + 8][kb + tg + 4];
            }
            uint32_t bf[4][2];
            #pragma unroll
            for (int in = 0; in < 4; in++) {
                const int c = warpN * 32 + in * 8 + g;
                bf[in][0] = Bs[buf][kb + tg    ][c];
                bf[in][1] = Bs[buf][kb + tg + 4][c];
            }
            #pragma unroll
            for (int im = 0; im < 4; im++)
                #pragma unroll
                for (int in = 0; in < 4; in++)
                    mma_tf32(acc[im][in], af[im], bf[in]);
        }

        if (kt + 1 < KT) {
            const int nb = 1 - buf;
            As[nb][ar][ac+0] = f2tf(pa0.x); As[nb][ar][ac+1] = f2tf(pa0.y);
            As[nb][ar][ac+2] = f2tf(pa0.z); As[nb][ar][ac+3] = f2tf(pa0.w);
            As[nb][ar][ac+4] = f2tf(pa1.x); As[nb][ar][ac+5] = f2tf(pa1.y);
            As[nb][ar][ac+6] = f2tf(pa1.z); As[nb][ar][ac+7] = f2tf(pa1.w);
            if (!TRANSB) {
                Bs[nb][bk][bn+0] = f2tf(pb0.x); Bs[nb][bk][bn+1] = f2tf(pb0.y);
                Bs[nb][bk][bn+2] = f2tf(pb0.z); Bs[nb][bk][bn+3] = f2tf(pb0.w);
                Bs[nb][bk][bn+4] = f2tf(pb1.x); Bs[nb][bk][bn+5] = f2tf(pb1.y);
                Bs[nb][bk][bn+6] = f2tf(pb1.z); Bs[nb][bk][bn+7] = f2tf(pb1.w);
            } else {
                Bs[nb][tkc+0][tnr] = f2tf(pb0.x); Bs[nb][tkc+1][tnr] = f2tf(pb0.y);
                Bs[nb][tkc+2][tnr] = f2tf(pb0.z); Bs[nb][tkc+3][tnr] = f2tf(pb0.w);
                Bs[nb][tkc+4][tnr] = f2tf(pb1.x); Bs[nb][tkc+5][tnr] = f2tf(pb1.y);
                Bs[nb][tkc+6][tnr] = f2tf(pb1.z); Bs[nb][tkc+7][tnr] = f2tf(pb1.w);
            }
            __syncthreads();
        }
    }

    // ---- epilogue ----
    #pragma unroll
    for (int im = 0; im < 4; im++) {
        #pragma unroll
        for (int half = 0; half < 2; half++) {
            const int gm = row0 + warpM * 64 + im * 16 + g + half * 8;
            float* crow = C + (long long)gm * ldc;
            const float* rrow = HASRES ? (resid + (long long)gm * ldc) : nullptr;
            #pragma unroll
            for (int in = 0; in < 4; in++) {
                const int gn = col0 + warpN * 32 + in * 8 + tg * 2;
                float2 v;
                v.x = acc[im][in][half * 2 + 0] * alpha;
                v.y = acc[im][in][half * 2 + 1] * alpha;
                if (HASBIAS) {
                    v.x += bias[gn];
                    v.y += bias[gn + 1];
                }
                if (HASRES) {
                    float2 rr = *(const float2*)(rrow + gn);
                    v.x += rr.x; v.y += rr.y;
                }
                *(float2*)(crow + gn) = v;
            }
        }
    }
}

// ---------------- generic batched SGEMM (small/odd shapes) ----------------
#define BM 64
#define BN 64
#define BKK 16

template<bool TRANSB, bool RELU, bool HASBIAS, bool HASRES, bool CAUSAL, bool CAUSALK>
__global__ __launch_bounds__(256)
void gemm_k(const float* __restrict__ A, const float* __restrict__ Bm,
            float* __restrict__ C,
            int M, int N, int K, int lda, int ldb, int ldc,
            int innerCnt,
            long long soA, long long siA,
            long long soB, long long siB,
            long long soC, long long siC,
            const float* __restrict__ bias,
            const float* __restrict__ resid,
            float alpha) {
    int row0 = blockIdx.y * BM;
    int col0 = blockIdx.x * BN;
    if (CAUSAL) {
        if (col0 > row0 + BM - 1) return;
    }
    int bz = blockIdx.z;
    int zo = bz / innerCnt;
    int zi = bz - zo * innerCnt;
    A  += zo * soA + zi * siA;
    Bm += zo * soB + zi * siB;
    C  += zo * soC + zi * siC;
    const float* R = resid;
    if (HASRES) R += zo * soC + zi * siC;

    __shared__ float As[BKK][BM];
    __shared__ float Bs[BKK][BN + 4];

    int tid = threadIdx.x;
    int tx = tid & 15;
    int ty = tid >> 4;
    float acc[4][4] = {};

    int Kend = K;
    if (CAUSALK) { int ke = row0 + BM; Kend = ke < K ? ke : K; }

    for (int k0 = 0; k0 < Kend; k0 += BKK) {
        #pragma unroll
        for (int i = 0; i < 4; i++) {
            int li = tid * 4 + i;
            int m = li >> 4, k = li & 15;
            int gm = row0 + m, gk = k0 + k;
            float v = 0.f;
            if (gm < M && gk < K) v = A[(long long)gm * lda + gk];
            As[k][m] = v;
        }
        if (!TRANSB) {
            #pragma unroll
            for (int i = 0; i < 4; i++) {
                int li = tid * 4 + i;
                int k = li >> 6, n = li & 63;
                int gk = k0 + k, gn = col0 + n;
                float v = 0.f;
                if (gk < K && gn < N) v = Bm[(long long)gk * ldb + gn];
                Bs[k][n] = v;
            }
        } else {
            #pragma unroll
            for (int i = 0; i < 4; i++) {
                int li = tid * 4 + i;
                int n = li >> 4, k = li & 15;
                int gn = col0 + n, gk = k0 + k;
                float v = 0.f;
                if (gn < N && gk < K) v = Bm[(long long)gn * ldb + gk];
                Bs[k][n] = v;
            }
        }
        __syncthreads();
        #pragma unroll
        for (int k = 0; k < BKK; k++) {
            float4 a4 = *(const float4*)&As[k][ty * 4];
            float4 b4 = *(const float4*)&Bs[k][tx * 4];
            float a[4] = {a4.x, a4.y, a4.z, a4.w};
            float b[4] = {b4.x, b4.y, b4.z, b4.w};
            #pragma unroll
            for (int i = 0; i < 4; i++)
                #pragma unroll
                for (int j = 0; j < 4; j++)
                    acc[i][j] = fmaf(a[i], b[j], acc[i][j]);
        }
        __syncthreads();
    }

    #pragma unroll
    for (int i = 0; i < 4; i++) {
        int gm = row0 + ty * 4 + i;
        if (gm >= M) continue;
        #pragma unroll
        for (int j = 0; j < 4; j++) {
            int gn = col0 + tx * 4 + j;
            if (gn >= N) continue;
            float v = acc[i][j] * alpha;
            if (HASBIAS) v += bias[gn];
            if (HASRES)  v += R[(long long)gm * ldc + gn];
            if (RELU)    v = fmaxf(v, 0.f);
            C[(long long)gm * ldc + gn] = v;
        }
    }
}

// ---------------- host launcher ----------------
extern "C" void kernel_launch(void* const* d_in, const int* in_sizes, int n_in,
                              void* d_out, int out_size) {
    const int*   idx   = (const int*)  d_in[0];
    const float* tok   = (const float*)d_in[1];
    const float* pos   = (const float*)d_in[2];
    const float* ln1_g = (const float*)d_in[3];
    const float* ln1_b = (const float*)d_in[4];
    const float* Wq    = (const float*)d_in[5];
    const float* Wk    = (const float*)d_in[6];
    const float* Wv    = (const float*)d_in[7];
    const float* Wo    = (const float*)d_in[8];
    const float* bo    = (const float*)d_in[9];
    const float* ln2_g = (const float*)d_in[10];
    const float* ln2_b = (const float*)d_in[11];
    const float* W1    = (const float*)d_in[12];
    const float* b1    = (const float*)d_in[13];
    const float* W2    = (const float*)d_in[14];
    const float* b2    = (const float*)d_in[15];
    const float* lnf_g = (const float*)d_in[16];
    const float* lnf_b = (const float*)d_in[17];
    const float* Wlm   = (const float*)d_in[18];

    float* out    = (float*)d_out;
    float* logits = out;                                  // (B,T,V)
    float* attn   = out + (long long)B_*T_*V_;            // (L,B,H,T,T)
    const long long ATTN1 = (long long)B_*H_*T_*T_;

    float *x, *h, *q, *k, *v, *y, *m;
    cudaGetSymbolAddress((void**)&x, g_x);
    cudaGetSymbolAddress((void**)&h, g_h);
    cudaGetSymbolAddress((void**)&q, g_q);
    cudaGetSymbolAddress((void**)&k, g_k);
    cudaGetSymbolAddress((void**)&v, g_v);
    cudaGetSymbolAddress((void**)&y, g_y);
    cudaGetSymbolAddress((void**)&m, g_m);

    // 1. embedding
    {
        int n = BT_*E_;
        embed_k<<<(n + 255) / 256, 256>>>(idx, tok, pos, x);
    }

    dim3 gE(E_ / 128, BT_ / 128);               // (4, 32)    QKV / proj
    dim3 gLM(V_ / 128, BT_ / 128);              // (250, 32)  lm head
    dim3 gS(T_ / 128, T_ / 128, B_*H_);         // (8, 8, 32) scores (tf32)
    dim3 gAV(1, T_ / 64, B_*H_);                // (1, 16,32) attn @ V
    dim3 gM1((HID_ + 63) / 64, BT_ / 64);       // (2, 64)    mlp1
    const float scale = 0.125f;                 // 1/sqrt(64)

    for (int l = 0; l < L_; l++) {
        float* attnL = attn + (long long)l * ATTN1;

        layernorm_k<<<BT_, 256>>>(x, ln1_g + l*E_, ln1_b + l*E_, h);

        // q/k/v = h @ W   (tf32 tensor cores)
        gemm_tf32_k<false,false,false,false><<<gE, 256>>>(
            h, Wq + (long long)l*E_*E_, q, BT_, E_, E_, E_, E_, E_,
            1, 0,0, 0,0, 0,0, nullptr, nullptr, 1.f);
        gemm_tf32_k<false,false,false,false><<<gE, 256>>>(
            h, Wk + (long long)l*E_*E_, k, BT_, E_, E_, E_, E_, E_,
            1, 0,0, 0,0, 0,0, nullptr, nullptr, 1.f);
        gemm_tf32_k<false,false,false,false><<<gE, 256>>>(
            h, Wv + (long long)l*E_*E_, v, BT_, E_, E_, E_, E_, E_,
            1, 0,0, 0,0, 0,0, nullptr, nullptr, 1.f);

        // scores = scale * Q @ K^T  (tf32, batched over b,h; causal tiles skipped)
        gemm_tf32_k<true,false,false,true><<<gS, 256>>>(
            q, k, attnL, T_, T_, HD_, E_, E_, T_,
            H_,
            (long long)T_*E_, (long long)HD_,
            (long long)T_*E_, (long long)HD_,
            (long long)H_*T_*T_, (long long)T_*T_,
            nullptr, nullptr, scale);

        softmax_causal_k<<<dim3(T_, B_*H_), 256>>>(attnL);

        // y = P @ V  (fp32, causal-K bound)
        gemm_k<false,false,false,false,false,true><<<gAV, 256>>>(
            attnL, v, y, T_, HD_, T_, T_, E_, E_,
            H_,
            (long long)H_*T_*T_, (long long)T_*T_,
            (long long)T_*E_, (long long)HD_,
            (long long)T_*E_, (long long)HD_,
            nullptr, nullptr, 1.f);

        // x = x + y @ Wo + bo   (tf32, fused bias+residual)
        gemm_tf32_k<false,true,true,false><<<gE, 256>>>(
            y, Wo + (long long)l*E_*E_, x, BT_, E_, E_, E_, E_, E_,
            1, 0,0, 0,0, 0,0, bo + l*E_, x, 1.f);

        layernorm_k<<<BT_, 256>>>(x, ln2_g + l*E_, ln2_b + l*E_, h);

        // m = relu(h @ W1 + b1)
        gemm_k<false,true,true,false,false,false><<<gM1, 256>>>(
            h, W1 + (long long)l*E_*HID_, m, BT_, HID_, E_, E_, HID_, HID_,
            1, 0,0, 0,0, 0,0, b1 + l*HID_, nullptr, 1.f);

        // x = x + m @ W2 + b2
        gemm_k<false,false,true,true,false,false><<<dim3(E_/64, BT_/64), 256>>>(
            m, W2 + (long long)l*HID_*E_, x, BT_, E_, HID_, HID_, E_, E_,
            1, 0,0, 0,0, 0,0, b2 + l*E_, x, 1.f);
    }

    // final LN + LM head (tf32)
    layernorm_k<<<BT_, 256>>>(x, lnf_g, lnf_b, h);
    gemm_tf32_k<false,false,false,false><<<gLM, 256>>>(
        h, Wlm, logits, BT_, V_, E_, E_, V_, V_,
        1, 0,0, 0,0, 0,0, nullptr, nullptr, 1.f);
}

// round 6
// speedup vs baseline: 2.7544x; 1.0395x over previous
#include <cuda_runtime.h>
#include <cstdint>

// Problem constants
#define B_   4
#define T_   1024
#define E_   512
#define H_   8
#define L_   4
#define V_   32000
#define HID_ 100
#define HD_  64
#define BT_  (B_*T_)

// ---------------- scratch (no allocations allowed) ----------------
__device__ float g_x[BT_*E_];
__device__ float g_h[BT_*E_];
__device__ float g_q[BT_*E_];
__device__ float g_k[BT_*E_];
__device__ float g_v[BT_*E_];
__device__ float g_y[BT_*E_];
__device__ float g_m[BT_*HID_];

// ---------------- block reductions ----------------
__device__ __forceinline__ float blockReduceSum(float v) {
    __shared__ float sh[32];
    int lane = threadIdx.x & 31, w = threadIdx.x >> 5;
    #pragma unroll
    for (int o = 16; o > 0; o >>= 1) v += __shfl_xor_sync(0xffffffffu, v, o);
    if (lane == 0) sh[w] = v;
    __syncthreads();
    v = (threadIdx.x < (blockDim.x >> 5)) ? sh[threadIdx.x] : 0.f;
    if (w == 0) {
        #pragma unroll
        for (int o = 16; o > 0; o >>= 1) v += __shfl_xor_sync(0xffffffffu, v, o);
        if (lane == 0) sh[0] = v;
    }
    __syncthreads();
    float r = sh[0];
    __syncthreads();
    return r;
}

__device__ __forceinline__ float blockReduceMax(float v) {
    __shared__ float sh[32];
    int lane = threadIdx.x & 31, w = threadIdx.x >> 5;
    #pragma unroll
    for (int o = 16; o > 0; o >>= 1) v = fmaxf(v, __shfl_xor_sync(0xffffffffu, v, o));
    if (lane == 0) sh[w] = v;
    __syncthreads();
    v = (threadIdx.x < (blockDim.x >> 5)) ? sh[threadIdx.x] : -1e30f;
    if (w == 0) {
        #pragma unroll
        for (int o = 16; o > 0; o >>= 1) v = fmaxf(v, __shfl_xor_sync(0xffffffffu, v, o));
        if (lane == 0) sh[0] = v;
    }
    __syncthreads();
    float r = sh[0];
    __syncthreads();
    return r;
}

// ---------------- embedding ----------------
__global__ void embed_k(const int* __restrict__ idx, const float* __restrict__ tok,
                        const float* __restrict__ pos, float* __restrict__ x) {
    int i = blockIdx.x * 256 + threadIdx.x;
    if (i >= BT_*E_) return;
    int e  = i & (E_-1);
    int bt = i >> 9;          // /E_
    int t  = bt & (T_-1);
    x[i] = tok[(long long)idx[bt]*E_ + e] + pos[t*E_ + e];
}

// ---------------- layernorm ----------------
__global__ void layernorm_k(const float* __restrict__ x, const float* __restrict__ g,
                            const float* __restrict__ bb, float* __restrict__ out) {
    const float* xr = x + (long long)blockIdx.x * E_;
    float v0 = xr[threadIdx.x], v1 = xr[threadIdx.x + 256];
    float mean = blockReduceSum(v0 + v1) * (1.f / E_);
    float d0 = v0 - mean, d1 = v1 - mean;
    float var = blockReduceSum(d0*d0 + d1*d1) * (1.f / E_);
    float rstd = rsqrtf(var + 1e-5f);
    float* o = out + (long long)blockIdx.x * E_;
    o[threadIdx.x]       = d0 * rstd * g[threadIdx.x]       + bb[threadIdx.x];
    o[threadIdx.x + 256] = d1 * rstd * g[threadIdx.x + 256] + bb[threadIdx.x + 256];
}

// ---------------- causal softmax, in-place ----------------
__global__ void softmax_causal_k(float* __restrict__ attn) {
    long long z = blockIdx.y;
    int t = blockIdx.x;
    float* row = attn + z * (long long)(T_*T_) + (long long)t * T_;
    int len = t + 1;
    float mx = -1e30f;
    for (int s = threadIdx.x; s < len; s += 256) mx = fmaxf(mx, row[s]);
    mx = blockReduceMax(mx);
    float sum = 0.f;
    for (int s = threadIdx.x; s < len; s += 256) sum += expf(row[s] - mx);
    sum = blockReduceSum(sum);
    float inv = 1.f / sum;
    for (int s = threadIdx.x; s < len; s += 256) row[s] = expf(row[s] - mx) * inv;
    for (int s = len + threadIdx.x; s < T_; s += 256) row[s] = 0.f;
}

// ============================================================================
// TF32 tensor-core GEMM, fragment-permuted A smem.
// 128x128 tile, BK=16, 8 warps each 64x32 via mma.m16n8k8.
// A fragments stored as uint4 per (ks, m16-tile, lane) with XOR lane swizzle:
//   p = lane ^ ((lane>>3)&3)   -> conflict-free stores AND LDS.128 loads.
// ============================================================================
__device__ __forceinline__ uint32_t f2tf(float f) {
    uint32_t r;
    asm("cvt.rna.tf32.f32 %0, %1;" : "=r"(r) : "f"(f));
    return r;
}

__device__ __forceinline__ void mma_tf32(float* c, const uint32_t* a, const uint32_t* b) {
    asm volatile(
      "mma.sync.aligned.m16n8k8.row.col.f32.tf32.tf32.f32 "
      "{%0,%1,%2,%3}, {%4,%5,%6,%7}, {%8,%9}, {%0,%1,%2,%3};\n"
      : "+f"(c[0]), "+f"(c[1]), "+f"(c[2]), "+f"(c[3])
      : "r"(a[0]), "r"(a[1]), "r"(a[2]), "r"(a[3]), "r"(b[0]), "r"(b[1]));
}

#define BPAD 136   // 16 k-rows x 136 (n stride) -> conflict-free B loads

struct TF32Smem {
    uint4    As[2][2][8][32];      // [buf][ks][mtile][swizzled lane]
    uint32_t Bs[2][16][BPAD];
};

// store one A value into the fragment layout
__device__ __forceinline__ void storeA(TF32Smem* S, int buf, int ks, int ar,
                                       int kk, uint32_t val) {
    const int mt = ar >> 4;
    const int within = ar & 15;
    const int rhalf = within >> 3;
    const int g = within & 7;
    const int tg = kk & 3;
    const int khalf = kk >> 2;
    const int lane = g * 4 + tg;
    const int p = lane ^ ((lane >> 3) & 3);
    const int slot = rhalf + 2 * khalf;
    ((uint32_t*)&S->As[buf][ks][mt][p])[slot] = val;
}

template<bool TRANSB, bool HASBIAS, bool HASRES>
__device__ __forceinline__
void gemm_tf32_body(const float* __restrict__ A, const float* __restrict__ Bm,
                    float* __restrict__ C,
                    int K, int lda, int ldb, int ldc,
                    const float* __restrict__ bias,
                    const float* __restrict__ resid,
                    float alpha, int row0, int col0) {
    __shared__ TF32Smem S;

    const int tid  = threadIdx.x;
    const int lane = tid & 31;
    const int wid  = tid >> 5;
    const int warpM = wid >> 2;          // 0..1
    const int warpN = wid & 3;           // 0..3
    const int g    = lane >> 2;
    const int tg   = lane & 3;
    const int plane = lane ^ ((lane >> 3) & 3);   // swizzled A-frag lane

    // staging addressing
    const int ar = tid >> 1;                       // A row in tile
    const int aks = tid & 1;                       // which ks half this thread stages
    const int bk = tid >> 4, bn = (tid & 15) * 8;  // B (KxN)
    const int tnr = tid >> 1, tkc = (tid & 1) * 8; // B (NxK transposed)

    float acc[4][4][4];
    #pragma unroll
    for (int i = 0; i < 4; i++)
        #pragma unroll
        for (int j = 0; j < 4; j++)
            #pragma unroll
            for (int r = 0; r < 4; r++) acc[i][j][r] = 0.f;

    const int KT = K >> 4;

    // ---- stage tile 0 ----
    {
        float4 a0 = *(const float4*)(A + (long long)(row0 + ar) * lda + aks * 8);
        float4 a1 = *(const float4*)(A + (long long)(row0 + ar) * lda + aks * 8 + 4);
        storeA(&S, 0, aks, ar, 0, f2tf(a0.x)); storeA(&S, 0, aks, ar, 1, f2tf(a0.y));
        storeA(&S, 0, aks, ar, 2, f2tf(a0.z)); storeA(&S, 0, aks, ar, 3, f2tf(a0.w));
        storeA(&S, 0, aks, ar, 4, f2tf(a1.x)); storeA(&S, 0, aks, ar, 5, f2tf(a1.y));
        storeA(&S, 0, aks, ar, 6, f2tf(a1.z)); storeA(&S, 0, aks, ar, 7, f2tf(a1.w));
        if (!TRANSB) {
            float4 b0 = *(const float4*)(Bm + (long long)bk * ldb + col0 + bn);
            float4 b1 = *(const float4*)(Bm + (long long)bk * ldb + col0 + bn + 4);
            S.Bs[0][bk][bn+0] = f2tf(b0.x); S.Bs[0][bk][bn+1] = f2tf(b0.y);
            S.Bs[0][bk][bn+2] = f2tf(b0.z); S.Bs[0][bk][bn+3] = f2tf(b0.w);
            S.Bs[0][bk][bn+4] = f2tf(b1.x); S.Bs[0][bk][bn+5] = f2tf(b1.y);
            S.Bs[0][bk][bn+6] = f2tf(b1.z); S.Bs[0][bk][bn+7] = f2tf(b1.w);
        } else {
            float4 b0 = *(const float4*)(Bm + (long long)(col0 + tnr) * ldb + tkc);
            float4 b1 = *(const float4*)(Bm + (long long)(col0 + tnr) * ldb + tkc + 4);
            S.Bs[0][tkc+0][tnr] = f2tf(b0.x); S.Bs[0][tkc+1][tnr] = f2tf(b0.y);
            S.Bs[0][tkc+2][tnr] = f2tf(b0.z); S.Bs[0][tkc+3][tnr] = f2tf(b0.w);
            S.Bs[0][tkc+4][tnr] = f2tf(b1.x); S.Bs[0][tkc+5][tnr] = f2tf(b1.y);
            S.Bs[0][tkc+6][tnr] = f2tf(b1.z); S.Bs[0][tkc+7][tnr] = f2tf(b1.w);
        }
    }
    __syncthreads();

    for (int kt = 0; kt < KT; kt++) {
        const int buf = kt & 1;
        float4 pa0, pa1, pb0, pb1;
        if (kt + 1 < KT) {
            const int kb = (kt + 1) * 16;
            pa0 = *(const float4*)(A + (long long)(row0 + ar) * lda + kb + aks * 8);
            pa1 = *(const float4*)(A + (long long)(row0 + ar) * lda + kb + aks * 8 + 4);
            if (!TRANSB) {
                pb0 = *(const float4*)(Bm + (long long)(kb + bk) * ldb + col0 + bn);
                pb1 = *(const float4*)(Bm + (long long)(kb + bk) * ldb + col0 + bn + 4);
            } else {
                pb0 = *(const float4*)(Bm + (long long)(col0 + tnr) * ldb + kb + tkc);
                pb1 = *(const float4*)(Bm + (long long)(col0 + tnr) * ldb + kb + tkc + 4);
            }
        }

        #pragma unroll
        for (int ks = 0; ks < 2; ks++) {
            const int kb = ks * 8;
            uint32_t af[4][4];
            #pragma unroll
            for (int im = 0; im < 4; im++) {
                uint4 v = S.As[buf][ks][warpM * 4 + im][plane];
                af[im][0] = v.x; af[im][1] = v.y; af[im][2] = v.z; af[im][3] = v.w;
            }
            uint32_t bf[4][2];
            #pragma unroll
            for (int in = 0; in < 4; in++) {
                const int c = warpN * 32 + in * 8 + g;
                bf[in][0] = S.Bs[buf][kb + tg    ][c];
                bf[in][1] = S.Bs[buf][kb + tg + 4][c];
            }
            #pragma unroll
            for (int im = 0; im < 4; im++)
                #pragma unroll
                for (int in = 0; in < 4; in++)
                    mma_tf32(acc[im][in], af[im], bf[in]);
        }

        if (kt + 1 < KT) {
            const int nb = 1 - buf;
            storeA(&S, nb, aks, ar, 0, f2tf(pa0.x)); storeA(&S, nb, aks, ar, 1, f2tf(pa0.y));
            storeA(&S, nb, aks, ar, 2, f2tf(pa0.z)); storeA(&S, nb, aks, ar, 3, f2tf(pa0.w));
            storeA(&S, nb, aks, ar, 4, f2tf(pa1.x)); storeA(&S, nb, aks, ar, 5, f2tf(pa1.y));
            storeA(&S, nb, aks, ar, 6, f2tf(pa1.z)); storeA(&S, nb, aks, ar, 7, f2tf(pa1.w));
            if (!TRANSB) {
                S.Bs[nb][bk][bn+0] = f2tf(pb0.x); S.Bs[nb][bk][bn+1] = f2tf(pb0.y);
                S.Bs[nb][bk][bn+2] = f2tf(pb0.z); S.Bs[nb][bk][bn+3] = f2tf(pb0.w);
                S.Bs[nb][bk][bn+4] = f2tf(pb1.x); S.Bs[nb][bk][bn+5] = f2tf(pb1.y);
                S.Bs[nb][bk][bn+6] = f2tf(pb1.z); S.Bs[nb][bk][bn+7] = f2tf(pb1.w);
            } else {
                S.Bs[nb][tkc+0][tnr] = f2tf(pb0.x); S.Bs[nb][tkc+1][tnr] = f2tf(pb0.y);
                S.Bs[nb][tkc+2][tnr] = f2tf(pb0.z); S.Bs[nb][tkc+3][tnr] = f2tf(pb0.w);
                S.Bs[nb][tkc+4][tnr] = f2tf(pb1.x); S.Bs[nb][tkc+5][tnr] = f2tf(pb1.y);
                S.Bs[nb][tkc+6][tnr] = f2tf(pb1.z); S.Bs[nb][tkc+7][tnr] = f2tf(pb1.w);
            }
            __syncthreads();
        }
    }

    // ---- epilogue ----
    #pragma unroll
    for (int im = 0; im < 4; im++) {
        #pragma unroll
        for (int half = 0; half < 2; half++) {
            const int gm = row0 + warpM * 64 + im * 16 + g + half * 8;
            float* crow = C + (long long)gm * ldc;
            const float* rrow = HASRES ? (resid + (long long)gm * ldc) : nullptr;
            #pragma unroll
            for (int in = 0; in < 4; in++) {
                const int gn = col0 + warpN * 32 + in * 8 + tg * 2;
                float2 v;
                v.x = acc[im][in][half * 2 + 0] * alpha;
                v.y = acc[im][in][half * 2 + 1] * alpha;
                if (HASBIAS) {
                    v.x += bias[gn];
                    v.y += bias[gn + 1];
                }
                if (HASRES) {
                    float2 rr = *(const float2*)(rrow + gn);
                    v.x += rr.x; v.y += rr.y;
                }
                *(float2*)(crow + gn) = v;
            }
        }
    }
}

// generic batched entry
template<bool TRANSB, bool HASBIAS, bool HASRES, bool CAUSAL>
__global__ __launch_bounds__(256, 2)
void gemm_tf32_k(const float* __restrict__ A, const float* __restrict__ Bm,
                 float* __restrict__ C,
                 int K, int lda, int ldb, int ldc,
                 int innerCnt,
                 long long soA, long long siA,
                 long long soB, long long siB,
                 long long soC, long long siC,
                 const float* __restrict__ bias,
                 const float* __restrict__ resid,
                 float alpha) {
    const int row0 = blockIdx.y * 128;
    const int col0 = blockIdx.x * 128;
    if (CAUSAL && col0 > row0 + 127) return;
    int bz = blockIdx.z;
    int zo = bz / innerCnt;
    int zi = bz - zo * innerCnt;
    A  += zo * soA + zi * siA;
    Bm += zo * soB + zi * siB;
    C  += zo * soC + zi * siC;
    if (HASRES) resid += zo * soC + zi * siC;
    gemm_tf32_body<TRANSB, HASBIAS, HASRES>(A, Bm, C, K, lda, ldb, ldc,
                                            bias, resid, alpha, row0, col0);
}

// fused QKV: blockIdx.z selects (W, out)
__global__ __launch_bounds__(256, 2)
void gemm_tf32_qkv_k(const float* __restrict__ A,
                     const float* __restrict__ W0, const float* __restrict__ W1,
                     const float* __restrict__ W2,
                     float* __restrict__ C0, float* __restrict__ C1,
                     float* __restrict__ C2) {
    const int row0 = blockIdx.y * 128;
    const int col0 = blockIdx.x * 128;
    const float* Bm = (blockIdx.z == 0) ? W0 : (blockIdx.z == 1) ? W1 : W2;
    float* C = (blockIdx.z == 0) ? C0 : (blockIdx.z == 1) ? C1 : C2;
    gemm_tf32_body<false, false, false>(A, Bm, C, E_, E_, E_, E_,
                                        nullptr, nullptr, 1.f, row0, col0);
}

// ---------------- generic batched SGEMM (small/odd shapes) ----------------
#define BM 64
#define BN 64
#define BKK 16

template<bool TRANSB, bool RELU, bool HASBIAS, bool HASRES, bool CAUSAL, bool CAUSALK>
__global__ __launch_bounds__(256)
void gemm_k(const float* __restrict__ A, const float* __restrict__ Bm,
            float* __restrict__ C,
            int M, int N, int K, int lda, int ldb, int ldc,
            int innerCnt,
            long long soA, long long siA,
            long long soB, long long siB,
            long long soC, long long siC,
            const float* __restrict__ bias,
            const float* __restrict__ resid,
            float alpha) {
    int row0 = blockIdx.y * BM;
    int col0 = blockIdx.x * BN;
    if (CAUSAL) {
        if (col0 > row0 + BM - 1) return;
    }
    int bz = blockIdx.z;
    int zo = bz / innerCnt;
    int zi = bz - zo * innerCnt;
    A  += zo * soA + zi * siA;
    Bm += zo * soB + zi * siB;
    C  += zo * soC + zi * siC;
    const float* R = resid;
    if (HASRES) R += zo * soC + zi * siC;

    __shared__ float As[BKK][BM];
    __shared__ float Bs[BKK][BN + 4];

    int tid = threadIdx.x;
    int tx = tid & 15;
    int ty = tid >> 4;
    float acc[4][4] = {};

    int Kend = K;
    if (CAUSALK) { int ke = row0 + BM; Kend = ke < K ? ke : K; }

    for (int k0 = 0; k0 < Kend; k0 += BKK) {
        #pragma unroll
        for (int i = 0; i < 4; i++) {
            int li = tid * 4 + i;
            int m = li >> 4, k = li & 15;
            int gm = row0 + m, gk = k0 + k;
            float v = 0.f;
            if (gm < M && gk < K) v = A[(long long)gm * lda + gk];
            As[k][m] = v;
        }
        if (!TRANSB) {
            #pragma unroll
            for (int i = 0; i < 4; i++) {
                int li = tid * 4 + i;
                int k = li >> 6, n = li & 63;
                int gk = k0 + k, gn = col0 + n;
                float v = 0.f;
                if (gk < K && gn < N) v = Bm[(long long)gk * ldb + gn];
                Bs[k][n] = v;
            }
        } else {
            #pragma unroll
            for (int i = 0; i < 4; i++) {
                int li = tid * 4 + i;
                int n = li >> 4, k = li & 15;
                int gn = col0 + n, gk = k0 + k;
                float v = 0.f;
                if (gn < N && gk < K) v = Bm[(long long)gn * ldb + gk];
                Bs[k][n] = v;
            }
        }
        __syncthreads();
        #pragma unroll
        for (int k = 0; k < BKK; k++) {
            float4 a4 = *(const float4*)&As[k][ty * 4];
            float4 b4 = *(const float4*)&Bs[k][tx * 4];
            float a[4] = {a4.x, a4.y, a4.z, a4.w};
            float b[4] = {b4.x, b4.y, b4.z, b4.w};
            #pragma unroll
            for (int i = 0; i < 4; i++)
                #pragma unroll
                for (int j = 0; j < 4; j++)
                    acc[i][j] = fmaf(a[i], b[j], acc[i][j]);
        }
        __syncthreads();
    }

    #pragma unroll
    for (int i = 0; i < 4; i++) {
        int gm = row0 + ty * 4 + i;
        if (gm >= M) continue;
        #pragma unroll
        for (int j = 0; j < 4; j++) {
            int gn = col0 + tx * 4 + j;
            if (gn >= N) continue;
            float v = acc[i][j] * alpha;
            if (HASBIAS) v += bias[gn];
            if (HASRES)  v += R[(long long)gm * ldc + gn];
            if (RELU)    v = fmaxf(v, 0.f);
            C[(long long)gm * ldc + gn] = v;
        }
    }
}

// ---------------- host launcher ----------------
extern "C" void kernel_launch(void* const* d_in, const int* in_sizes, int n_in,
                              void* d_out, int out_size) {
    const int*   idx   = (const int*)  d_in[0];
    const float* tok   = (const float*)d_in[1];
    const float* pos   = (const float*)d_in[2];
    const float* ln1_g = (const float*)d_in[3];
    const float* ln1_b = (const float*)d_in[4];
    const float* Wq    = (const float*)d_in[5];
    const float* Wk    = (const float*)d_in[6];
    const float* Wv    = (const float*)d_in[7];
    const float* Wo    = (const float*)d_in[8];
    const float* bo    = (const float*)d_in[9];
    const float* ln2_g = (const float*)d_in[10];
    const float* ln2_b = (const float*)d_in[11];
    const float* W1    = (const float*)d_in[12];
    const float* b1    = (const float*)d_in[13];
    const float* W2    = (const float*)d_in[14];
    const float* b2    = (const float*)d_in[15];
    const float* lnf_g = (const float*)d_in[16];
    const float* lnf_b = (const float*)d_in[17];
    const float* Wlm   = (const float*)d_in[18];

    float* out    = (float*)d_out;
    float* logits = out;                                  // (B,T,V)
    float* attn   = out + (long long)B_*T_*V_;            // (L,B,H,T,T)
    const long long ATTN1 = (long long)B_*H_*T_*T_;

    float *x, *h, *q, *k, *v, *y, *m;
    cudaGetSymbolAddress((void**)&x, g_x);
    cudaGetSymbolAddress((void**)&h, g_h);
    cudaGetSymbolAddress((void**)&q, g_q);
    cudaGetSymbolAddress((void**)&k, g_k);
    cudaGetSymbolAddress((void**)&v, g_v);
    cudaGetSymbolAddress((void**)&y, g_y);
    cudaGetSymbolAddress((void**)&m, g_m);

    // 1. embedding
    {
        int n = BT_*E_;
        embed_k<<<(n + 255) / 256, 256>>>(idx, tok, pos, x);
    }

    dim3 gE(E_ / 128, BT_ / 128);               // (4, 32)    proj
    dim3 gQKV(E_ / 128, BT_ / 128, 3);          // (4, 32, 3) fused QKV
    dim3 gLM(V_ / 128, BT_ / 128);              // (250, 32)  lm head
    dim3 gS(T_ / 128, T_ / 128, B_*H_);         // (8, 8, 32) scores (tf32)
    dim3 gAV(1, T_ / 64, B_*H_);                // (1, 16,32) attn @ V
    dim3 gM1((HID_ + 63) / 64, BT_ / 64);       // (2, 64)    mlp1
    const float scale = 0.125f;                 // 1/sqrt(64)

    for (int l = 0; l < L_; l++) {
        float* attnL = attn + (long long)l * ATTN1;

        layernorm_k<<<BT_, 256>>>(x, ln1_g + l*E_, ln1_b + l*E_, h);

        // q/k/v = h @ W   (fused, one launch)
        gemm_tf32_qkv_k<<<gQKV, 256>>>(
            h, Wq + (long long)l*E_*E_, Wk + (long long)l*E_*E_,
            Wv + (long long)l*E_*E_, q, k, v);

        // scores = scale * Q @ K^T
        gemm_tf32_k<true,false,false,true><<<gS, 256>>>(
            q, k, attnL, HD_, E_, E_, T_,
            H_,
            (long long)T_*E_, (long long)HD_,
            (long long)T_*E_, (long long)HD_,
            (long long)H_*T_*T_, (long long)T_*T_,
            nullptr, nullptr, scale);

        softmax_causal_k<<<dim3(T_, B_*H_), 256>>>(attnL);

        // y = P @ V  (fp32, causal-K bound)
        gemm_k<false,false,false,false,false,true><<<gAV, 256>>>(
            attnL, v, y, T_, HD_, T_, T_, E_, E_,
            H_,
            (long long)H_*T_*T_, (long long)T_*T_,
            (long long)T_*E_, (long long)HD_,
            (long long)T_*E_, (long long)HD_,
            nullptr, nullptr, 1.f);

        // x = x + y @ Wo + bo
        gemm_tf32_k<false,true,true,false><<<gE, 256>>>(
            y, Wo + (long long)l*E_*E_, x, E_, E_, E_, E_,
            1, 0,0, 0,0, 0,0, bo + l*E_, x, 1.f);

        layernorm_k<<<BT_, 256>>>(x, ln2_g + l*E_, ln2_b + l*E_, h);

        // m = relu(h @ W1 + b1)
        gemm_k<false,true,true,false,false,false><<<gM1, 256>>>(
            h, W1 + (long long)l*E_*HID_, m, BT_, HID_, E_, E_, HID_, HID_,
            1, 0,0, 0,0, 0,0, b1 + l*HID_, nullptr, 1.f);

        // x = x + m @ W2 + b2
        gemm_k<false,false,true,true,false,false><<<dim3(E_/64, BT_/64), 256>>>(
            m, W2 + (long long)l*HID_*E_, x, BT_, E_, HID_, HID_, E_, E_,
            1, 0,0, 0,0, 0,0, b2 + l*E_, x, 1.f);
    }

    // final LN + LM head (tf32)
    layernorm_k<<<BT_, 256>>>(x, lnf_g, lnf_b, h);
    gemm_tf32_k<false,false,false,false><<<gLM, 256>>>(
        h, Wlm, logits, E_, E_, V_, V_,
        1, 0,0, 0,0, 0,0, nullptr, nullptr, 1.f);
}